// round 13
// baseline (speedup 1.0000x reference)
#include <cuda_runtime.h>
#include <cuda_fp16.h>
#include <cstdint>

// Problem constants: qkv (B,S,3,H,D) fp32
#define B_   2
#define S_   2048
#define H_   16
#define D_   64
#define BH_  32

#define U_SCALE   0.0625f
#define U_UNSCALE 16.0f

__device__ uint32_t g_q[(size_t)BH_ * S_ * 32];
__device__ uint32_t g_k[(size_t)BH_ * S_ * 32];
__device__ uint32_t g_v[(size_t)BH_ * S_ * 32];

__device__ __forceinline__ uint32_t smem_u32(const void* p) {
    uint32_t a;
    asm("{ .reg .u64 t; cvta.to.shared.u64 t, %1; cvt.u32.u64 %0, t; }" : "=r"(a) : "l"(p));
    return a;
}
__device__ __forceinline__ uint32_t sw128(uint32_t off) { return off ^ ((off >> 3) & 0x70); }

__device__ __forceinline__ uint32_t pack_f16(float x0, float x1) {
    uint32_t r;
    asm("cvt.rn.f16x2.f32 %0, %1, %2;" : "=r"(r) : "f"(x1), "f"(x0));
    return r;
}

// ---------------------------------------------------------------------------
// ldmatrix / mma (fragment mappings validated rounds 3-12)
// ---------------------------------------------------------------------------
__device__ __forceinline__ void ldsm_x4(uint32_t base, int r_base, int c_base, int lane, uint32_t r[4]) {
    uint32_t off = (uint32_t)((r_base + (lane & 15)) * 128 + (c_base + ((lane >> 4) << 3)) * 2);
    uint32_t addr = base + sw128(off);
    asm volatile("ldmatrix.sync.aligned.m8n8.x4.shared.b16 {%0,%1,%2,%3}, [%4];"
                 : "=r"(r[0]), "=r"(r[1]), "=r"(r[2]), "=r"(r[3]) : "r"(addr));
}
__device__ __forceinline__ void ldsm_x4_t(uint32_t base, int r_base, int c_base, int lane, uint32_t r[4]) {
    uint32_t off = (uint32_t)((r_base + (lane & 15)) * 128 + (c_base + ((lane >> 4) << 3)) * 2);
    uint32_t addr = base + sw128(off);
    asm volatile("ldmatrix.sync.aligned.m8n8.x4.trans.shared.b16 {%0,%1,%2,%3}, [%4];"
                 : "=r"(r[0]), "=r"(r[1]), "=r"(r[2]), "=r"(r[3]) : "r"(addr));
}
__device__ __forceinline__ void mma16816(float c[4], const uint32_t a[4], const uint32_t b[2]) {
    asm volatile("mma.sync.aligned.m16n8k16.row.col.f32.f16.f16.f32 "
                 "{%0,%1,%2,%3}, {%4,%5,%6,%7}, {%8,%9}, {%0,%1,%2,%3};"
                 : "+f"(c[0]), "+f"(c[1]), "+f"(c[2]), "+f"(c[3])
                 : "r"(a[0]), "r"(a[1]), "r"(a[2]), "r"(a[3]), "r"(b[0]), "r"(b[1]));
}

// load stage1 B-frags for one 32-row half: bf[kd][nf(4)][2]
__device__ __forceinline__ void load_b1_half(uint32_t kb, int rbase, int lane, uint32_t bf[4][4][2]) {
#pragma unroll
    for (int kd = 0; kd < 4; kd++) {
        uint32_t r0[4], r1[4];
        ldsm_x4(kb, rbase,      kd * 16, lane, r0);
        ldsm_x4(kb, rbase + 16, kd * 16, lane, r1);
        bf[kd][0][0] = r0[0]; bf[kd][0][1] = r0[2];
        bf[kd][1][0] = r0[1]; bf[kd][1][1] = r0[3];
        bf[kd][2][0] = r1[0]; bf[kd][2][1] = r1[2];
        bf[kd][3][0] = r1[1]; bf[kd][3][1] = r1[3];
    }
}
// load stage2 B-frags for two ks slices: bf[ks(2)][nf(8)][2]
__device__ __forceinline__ void load_b2_pair(uint32_t s2b, int ksbase, int lane, uint32_t bf[2][8][2]) {
#pragma unroll
    for (int ks = 0; ks < 2; ks++) {
#pragma unroll
        for (int nq = 0; nq < 4; nq++) {
            uint32_t r[4];
            ldsm_x4_t(s2b, (ksbase + ks) * 16, nq * 16, lane, r);
            bf[ks][2*nq][0] = r[0]; bf[ks][2*nq][1] = r[1];
            bf[ks][2*nq+1][0] = r[2]; bf[ks][2*nq+1][1] = r[3];
        }
    }
}

// mask one 32-col half tile s1h[mi][nf(4)][4]; columns colbase..colbase+31
__device__ __forceinline__ void mask_halft(float (&s1h)[2][4][4], int colbase, int t0, int cp0) {
#pragma unroll
    for (int mi = 0; mi < 2; mi++)
#pragma unroll
        for (int nf = 0; nf < 4; nf++)
#pragma unroll
            for (int e = 0; e < 4; e++) {
                int srow = t0 + mi * 16 + ((e >> 1) << 3);
                int scol = colbase + nf * 8 + cp0 + (e & 1);
                if (scol > srow) s1h[mi][nf][e] = 0.0f;
            }
}
// convert half tile -> af[mi][kf(2)][4]
__device__ __forceinline__ void conv_halft(const float (&s1h)[2][4][4], uint32_t (&af)[2][2][4]) {
#pragma unroll
    for (int mi = 0; mi < 2; mi++)
#pragma unroll
        for (int kf = 0; kf < 2; kf++) {
            af[mi][kf][0] = pack_f16(s1h[mi][2*kf  ][0], s1h[mi][2*kf  ][1]);
            af[mi][kf][1] = pack_f16(s1h[mi][2*kf  ][2], s1h[mi][2*kf  ][3]);
            af[mi][kf][2] = pack_f16(s1h[mi][2*kf+1][0], s1h[mi][2*kf+1][1]);
            af[mi][kf][3] = pack_f16(s1h[mi][2*kf+1][2], s1h[mi][2*kf+1][3]);
        }
}

// ---------------------------------------------------------------------------
// One 64-col chunk, m32 warp tile, software-pipelined B-fragment loads.
// ---------------------------------------------------------------------------
__device__ __forceinline__ void chunk_gemm(uint32_t kb, uint32_t s2b,
                                           const uint32_t (&aF)[2][4][4], float (&acc)[2][8][4],
                                           int lane, int t0, int cp0, int colbase, bool diag) {
    // 1. load bfA (stage1 half0) + bfB (stage1 half1)
    uint32_t bfA[4][4][2], bfB[4][4][2];
    load_b1_half(kb, 0, lane, bfA);
    load_b1_half(kb, 32, lane, bfB);

    // 3. MMA_A: s1a[mi][nf] over kd (half0 cols)
    float s1a[2][4][4] = {};
#pragma unroll
    for (int kd = 0; kd < 4; kd++)
#pragma unroll
        for (int mi = 0; mi < 2; mi++)
#pragma unroll
            for (int nf = 0; nf < 4; nf++)
                mma16816(s1a[mi][nf], aF[mi][kd], bfA[kd][nf]);

    // 4. load bfC (stage2 ks0,1) -- overlaps MMA_A drain
    uint32_t bfC[2][8][2];
    load_b2_pair(s2b, 0, lane, bfC);

    // 5. mask + conv half0 -> af01
    uint32_t af01[2][2][4];
    if (diag) mask_halft(s1a, colbase, t0, cp0);
    conv_halft(s1a, af01);

    // 6. MMA_B: s1b over kd (half1 cols); bfB loaded long ago
    float s1b[2][4][4] = {};
#pragma unroll
    for (int kd = 0; kd < 4; kd++)
#pragma unroll
        for (int mi = 0; mi < 2; mi++)
#pragma unroll
            for (int nf = 0; nf < 4; nf++)
                mma16816(s1b[mi][nf], aF[mi][kd], bfB[kd][nf]);

    // 7. load bfD (stage2 ks2,3) -- overlaps MMA_B drain
    uint32_t bfD[2][8][2];
    load_b2_pair(s2b, 2, lane, bfD);

    // 8. MMA_C: acc += af01 x bfC  (ks 0,1)
#pragma unroll
    for (int ks = 0; ks < 2; ks++)
#pragma unroll
        for (int mi = 0; mi < 2; mi++)
#pragma unroll
            for (int nf = 0; nf < 8; nf++)
                mma16816(acc[mi][nf], af01[mi][ks], bfC[ks][nf]);

    // 9. mask + conv half1 -> af23 (overlaps MMA_C drain)
    uint32_t af23[2][2][4];
    if (diag) mask_halft(s1b, colbase + 32, t0, cp0);
    conv_halft(s1b, af23);

    // 10. MMA_D: acc += af23 x bfD  (ks 2,3)
#pragma unroll
    for (int ks = 0; ks < 2; ks++)
#pragma unroll
        for (int mi = 0; mi < 2; mi++)
#pragma unroll
            for (int nf = 0; nf < 8; nf++)
                mma16816(acc[mi][nf], af23[mi][ks], bfD[ks][nf]);
}

// ---------------------------------------------------------------------------
// cp.async: single 64-row x 128B panel, SW128 swizzled (128 threads)
// ---------------------------------------------------------------------------
__device__ __forceinline__ void cpa16(uint32_t smaddr, const void* gaddr) {
    asm volatile("cp.async.cg.shared.global [%0], [%1], 16;" :: "r"(smaddr), "l"(gaddr));
}
__device__ __forceinline__ void issue_panel1(const uint32_t* g, uint32_t sm, int tid) {
    for (int i = tid; i < 512; i += 128) {
        int r = i >> 3, c = i & 7;
        uint32_t off = sw128((uint32_t)(r * 128 + c * 16));
        cpa16(sm + off, g + r * 32 + c * 4);
    }
}
#define CP_COMMIT() asm volatile("cp.async.commit_group;" ::: "memory")
#define CP_WAIT1()  asm volatile("cp.async.wait_group 1;" ::: "memory")
#define CP_WAIT0()  asm volatile("cp.async.wait_group 0;" ::: "memory")

__device__ __forceinline__ void stage_panel1(const uint32_t* g, char* sm, int rows, int tid) {
    for (int idx = tid; idx < rows * 32; idx += 128) {
        int r = idx >> 5, c = idx & 31;
        uint32_t off = sw128((uint32_t)(r * 128 + c * 4));
        *reinterpret_cast<uint32_t*>(sm + off) = g[r * 32 + c];
    }
}

// ===========================================================================
// Preprocess: qkv fp32 -> fp16 (q, k, v), head-major rows of 64
// ===========================================================================
__global__ __launch_bounds__(256) void prep(const float* __restrict__ qkv) {
    int idx = blockIdx.x * 256 + threadIdx.x;
    int c2 = idx & 31;
    int h  = (idx >> 5) & 15;
    int w  = (idx >> 9) % 3;
    int sb = idx / 1536;
    int s  = sb & (S_ - 1);
    int b  = sb >> 11;
    float2 v = *reinterpret_cast<const float2*>(qkv + (size_t)idx * 2);
    size_t dst = ((size_t)(b * 16 + h) * S_ + s) * 32 + c2;
    uint32_t p = pack_f16(v.x, v.y);
    if (w == 0)      g_q[dst] = p;
    else if (w == 1) g_k[dst] = p;
    else             g_v[dst] = p;
}

// smem: V ring [0,24K) (q staging [0,16K) aliases V0/V1, dead before phase 2)
//       K ring [24K,48K)
#define SMQ 0
#define SMV(st) ((st) * 8192)
#define SMK(st) (24576 + (st) * 8192)
#define SMEM_BYTES 49152

// ===========================================================================
// Fused, 128 threads / 4 warps, m32 warp tiles, pipelined B-frag loads.
// phase 1: o2 = tril(q kT) k, u = (2q-o2)/16 in REGISTERS
// phase 2: out = tril(u kT) v * 16
// ===========================================================================
__global__ __launch_bounds__(128, 2) void fused(float* __restrict__ out) {
    int bh = blockIdx.y, tt = 15 - (int)blockIdx.x;
    extern __shared__ __align__(1024) char smem[];
    uint32_t sb = smem_u32(smem);
    int tid = threadIdx.x, lane = tid & 31, wid = tid >> 5;
    int warp_m = wid * 32;
    int b = bh >> 4, h = bh & 15;
    int nch = 2 * tt + 2;

    const uint32_t* k0 = g_k + (size_t)bh * S_ * 32;
    const uint32_t* v0 = g_v + (size_t)bh * S_ * 32;

    // prologue: stage q, prefetch k chunks 0 and 1
    const uint32_t* qG = g_q + ((size_t)bh * S_ + tt * 128) * 32;
    stage_panel1(qG, smem + SMQ, 128, tid);
    issue_panel1(k0, sb + SMK(0), tid);
    CP_COMMIT();
    issue_panel1(k0 + 2048, sb + SMK(1), tid);
    CP_COMMIT();
    __syncthreads();

    uint32_t qf[2][4][4];
#pragma unroll
    for (int mi = 0; mi < 2; mi++)
#pragma unroll
        for (int kf = 0; kf < 4; kf++)
            ldsm_x4(sb + SMQ, warp_m + mi * 16, kf * 16, lane, qf[mi][kf]);

    int t0 = tt * 128 + warp_m + (lane >> 2);
    int cp0 = (lane & 3) * 2;
    int row_hi = tt * 128 + warp_m + 31;

    // ---------------- phase 1: o2 ----------------
    float o2acc[2][8][4] = {};
    for (int ch = 0; ch < nch; ch++) {
        if (ch + 1 < nch) CP_WAIT1(); else CP_WAIT0();
        __syncthreads();
        if (ch + 2 < nch) {
            issue_panel1(k0 + (size_t)(ch + 2) * 2048, sb + SMK((ch + 2) % 3), tid);
            CP_COMMIT();
        }
        if (ch * 64 <= row_hi) {
            uint32_t kb = sb + SMK(ch % 3);
            chunk_gemm(kb, kb, qf, o2acc, lane, t0, cp0, ch * 64, ch >= 2 * tt);
        }
    }

    // phase-2 prefetch before u-conversion (overlap DMA with math)
    int kb0 = nch % 3;
    issue_panel1(k0, sb + SMK(kb0), tid);
    issue_panel1(v0, sb + SMV(0), tid);
    CP_COMMIT();
    issue_panel1(k0 + 2048, sb + SMK((kb0 + 1) % 3), tid);
    issue_panel1(v0 + 2048, sb + SMV(1), tid);
    CP_COMMIT();

    // u = (2q - o2) * U_SCALE directly into A-frags (acc layout == A-frag layout)
    uint32_t uf[2][4][4];
#pragma unroll
    for (int mi = 0; mi < 2; mi++) {
        float uacc[8][4];
#pragma unroll
        for (int nf = 0; nf < 8; nf++)
#pragma unroll
            for (int half = 0; half < 2; half++) {
                int reg = ((nf & 1) << 1) | half;
                uint32_t qb = qf[mi][nf >> 1][reg];
                float q0 = __half2float(__ushort_as_half((unsigned short)(qb & 0xFFFF)));
                float q1 = __half2float(__ushort_as_half((unsigned short)(qb >> 16)));
                uacc[nf][half * 2 + 0] = (2.0f * q0 - o2acc[mi][nf][half * 2 + 0]) * U_SCALE;
                uacc[nf][half * 2 + 1] = (2.0f * q1 - o2acc[mi][nf][half * 2 + 1]) * U_SCALE;
            }
#pragma unroll
        for (int kf = 0; kf < 4; kf++) {
            uf[mi][kf][0] = pack_f16(uacc[2*kf  ][0], uacc[2*kf  ][1]);
            uf[mi][kf][1] = pack_f16(uacc[2*kf  ][2], uacc[2*kf  ][3]);
            uf[mi][kf][2] = pack_f16(uacc[2*kf+1][0], uacc[2*kf+1][1]);
            uf[mi][kf][3] = pack_f16(uacc[2*kf+1][2], uacc[2*kf+1][3]);
        }
    }

    // ---------------- phase 2: out ----------------
    float outacc[2][8][4] = {};
    for (int ch = 0; ch < nch; ch++) {
        if (ch + 1 < nch) CP_WAIT1(); else CP_WAIT0();
        __syncthreads();
        if (ch + 2 < nch) {
            issue_panel1(k0 + (size_t)(ch + 2) * 2048, sb + SMK((kb0 + ch + 2) % 3), tid);
            issue_panel1(v0 + (size_t)(ch + 2) * 2048, sb + SMV((ch + 2) % 3), tid);
            CP_COMMIT();
        }
        if (ch * 64 <= row_hi) {
            uint32_t kb = sb + SMK((kb0 + ch) % 3);
            uint32_t vb = sb + SMV(ch % 3);
            chunk_gemm(kb, vb, uf, outacc, lane, t0, cp0, ch * 64, ch >= 2 * tt);
        }
    }

    // out (B,S,H,D) fp32, undo U_SCALE
#pragma unroll
    for (int mi = 0; mi < 2; mi++)
#pragma unroll
        for (int half = 0; half < 2; half++) {
            int t = t0 + mi * 16 + half * 8;
            float* op = out + (((size_t)(b * S_ + t)) * 16 + h) * 64;
#pragma unroll
            for (int nf = 0; nf < 8; nf++) {
                float2 v = make_float2(outacc[mi][nf][half * 2 + 0] * U_UNSCALE,
                                       outacc[mi][nf][half * 2 + 1] * U_UNSCALE);
                *reinterpret_cast<float2*>(op + nf * 8 + cp0) = v;
            }
        }
}

// ===========================================================================
extern "C" void kernel_launch(void* const* d_in, const int* in_sizes, int n_in,
                              void* d_out, int out_size) {
    const float* qkv = (const float*)d_in[0];
    float* out = (float*)d_out;

    static bool attr_done = false;
    if (!attr_done) {
        cudaFuncSetAttribute(fused, cudaFuncAttributeMaxDynamicSharedMemorySize, SMEM_BYTES);
        attr_done = true;
    }

    prep<<<B_ * S_ * 3 * H_ * 32 / 256, 256>>>(qkv);
    dim3 grid(16, BH_);
    fused<<<grid, 128, SMEM_BYTES>>>(out);
}

// round 15
// speedup vs baseline: 1.0801x; 1.0801x over previous
#include <cuda_runtime.h>
#include <cuda_fp16.h>
#include <cstdint>

// Problem constants: qkv (B,S,3,H,D) fp32
#define B_   2
#define S_   2048
#define H_   16
#define D_   64
#define BH_  32

#define U_SCALE   0.0625f
#define U_UNSCALE 16.0f

__device__ uint32_t g_k[(size_t)BH_ * S_ * 32];
__device__ uint32_t g_v[(size_t)BH_ * S_ * 32];

__device__ __forceinline__ uint32_t smem_u32(const void* p) {
    uint32_t a;
    asm("{ .reg .u64 t; cvta.to.shared.u64 t, %1; cvt.u32.u64 %0, t; }" : "=r"(a) : "l"(p));
    return a;
}
__device__ __forceinline__ uint32_t sw128(uint32_t off) { return off ^ ((off >> 3) & 0x70); }

__device__ __forceinline__ uint32_t pack_f16(float x0, float x1) {
    uint32_t r;
    asm("cvt.rn.f16x2.f32 %0, %1, %2;" : "=r"(r) : "f"(x1), "f"(x0));
    return r;
}

// ---------------------------------------------------------------------------
// ldmatrix / mma (fragment mappings validated rounds 3-13)
// ---------------------------------------------------------------------------
__device__ __forceinline__ void ldsm_x4(uint32_t base, int r_base, int c_base, int lane, uint32_t r[4]) {
    uint32_t off = (uint32_t)((r_base + (lane & 15)) * 128 + (c_base + ((lane >> 4) << 3)) * 2);
    uint32_t addr = base + sw128(off);
    asm volatile("ldmatrix.sync.aligned.m8n8.x4.shared.b16 {%0,%1,%2,%3}, [%4];"
                 : "=r"(r[0]), "=r"(r[1]), "=r"(r[2]), "=r"(r[3]) : "r"(addr));
}
__device__ __forceinline__ void ldsm_x4_t(uint32_t base, int r_base, int c_base, int lane, uint32_t r[4]) {
    uint32_t off = (uint32_t)((r_base + (lane & 15)) * 128 + (c_base + ((lane >> 4) << 3)) * 2);
    uint32_t addr = base + sw128(off);
    asm volatile("ldmatrix.sync.aligned.m8n8.x4.trans.shared.b16 {%0,%1,%2,%3}, [%4];"
                 : "=r"(r[0]), "=r"(r[1]), "=r"(r[2]), "=r"(r[3]) : "r"(addr));
}
__device__ __forceinline__ void mma16816(float c[4], const uint32_t a[4], const uint32_t b[2]) {
    asm volatile("mma.sync.aligned.m16n8k16.row.col.f32.f16.f16.f32 "
                 "{%0,%1,%2,%3}, {%4,%5,%6,%7}, {%8,%9}, {%0,%1,%2,%3};"
                 : "+f"(c[0]), "+f"(c[1]), "+f"(c[2]), "+f"(c[3])
                 : "r"(a[0]), "r"(a[1]), "r"(a[2]), "r"(a[3]), "r"(b[0]), "r"(b[1]));
}

// B-frags, trans ([k][n]), n=64 (stage 2)
__device__ __forceinline__ void load_b_t1(uint32_t base, int kk, int lane, uint32_t bf[8][2]) {
#pragma unroll
    for (int nq = 0; nq < 4; nq++) {
        uint32_t r[4];
        ldsm_x4_t(base, kk, nq * 16, lane, r);
        bf[2*nq][0] = r[0]; bf[2*nq][1] = r[1]; bf[2*nq+1][0] = r[2]; bf[2*nq+1][1] = r[3];
    }
}

// mask a half (4 nf frags starting at nfbase) of one m16 subtile
__device__ __forceinline__ void mask_half(float (&s1)[8][4], int nfbase, int colbase,
                                          int t0mi, int cp0) {
#pragma unroll
    for (int nf = 0; nf < 4; nf++)
#pragma unroll
        for (int e = 0; e < 4; e++) {
            int srow = t0mi + ((e >> 1) << 3);
            int scol = colbase + (nfbase + nf) * 8 + cp0 + (e & 1);
            if (scol > srow) s1[nfbase + nf][e] = 0.0f;
        }
}
// conv a half: s1[2kf],s1[2kf+1] -> af[kf], for kf in {kfbase, kfbase+1}
__device__ __forceinline__ void conv_half(const float (&s1)[8][4], uint32_t (&af)[4][4], int kfbase) {
#pragma unroll
    for (int kf = kfbase; kf < kfbase + 2; kf++) {
        af[kf][0] = pack_f16(s1[2*kf  ][0], s1[2*kf  ][1]);
        af[kf][1] = pack_f16(s1[2*kf  ][2], s1[2*kf  ][3]);
        af[kf][2] = pack_f16(s1[2*kf+1][0], s1[2*kf+1][1]);
        af[kf][3] = pack_f16(s1[2*kf+1][2], s1[2*kf+1][3]);
    }
}

// ---------------------------------------------------------------------------
// One 64-col chunk for an m32 warp tile (R12-proven body)
// ---------------------------------------------------------------------------
__device__ __forceinline__ void chunk_gemm(uint32_t kb, uint32_t s2b,
                                           const uint32_t (&aF)[2][4][4], float (&acc)[2][8][4],
                                           int lane, int t0, int cp0, int colbase, bool diag) {
    float s1[2][8][4] = {};
#pragma unroll
    for (int kd = 0; kd < 4; kd++) {
        uint32_t r0[4], r1[4];
        ldsm_x4(kb, 0,  kd * 16, lane, r0);
        ldsm_x4(kb, 16, kd * 16, lane, r1);
        uint32_t bf[4][2];
        bf[0][0] = r0[0]; bf[0][1] = r0[2]; bf[1][0] = r0[1]; bf[1][1] = r0[3];
        bf[2][0] = r1[0]; bf[2][1] = r1[2]; bf[3][0] = r1[1]; bf[3][1] = r1[3];
#pragma unroll
        for (int mi = 0; mi < 2; mi++)
#pragma unroll
            for (int nf = 0; nf < 4; nf++) mma16816(s1[mi][nf], aF[mi][kd], bf[nf]);
    }
#pragma unroll
    for (int kd = 0; kd < 4; kd++) {
        uint32_t r0[4], r1[4];
        ldsm_x4(kb, 32, kd * 16, lane, r0);
        ldsm_x4(kb, 48, kd * 16, lane, r1);
        uint32_t bf[4][2];
        bf[0][0] = r0[0]; bf[0][1] = r0[2]; bf[1][0] = r0[1]; bf[1][1] = r0[3];
        bf[2][0] = r1[0]; bf[2][1] = r1[2]; bf[3][0] = r1[1]; bf[3][1] = r1[3];
#pragma unroll
        for (int mi = 0; mi < 2; mi++)
#pragma unroll
            for (int nf = 0; nf < 4; nf++) mma16816(s1[mi][4 + nf], aF[mi][kd], bf[nf]);
    }
    uint32_t af[2][4][4];
#pragma unroll
    for (int mi = 0; mi < 2; mi++) {
        if (diag) mask_half(s1[mi], 0, colbase, t0 + mi * 16, cp0);
        conv_half(s1[mi], af[mi], 0);
    }
#pragma unroll
    for (int ks = 0; ks < 2; ks++) {
        uint32_t bf[8][2];
        load_b_t1(s2b, ks * 16, lane, bf);
#pragma unroll
        for (int mi = 0; mi < 2; mi++)
#pragma unroll
            for (int nf = 0; nf < 8; nf++) mma16816(acc[mi][nf], af[mi][ks], bf[nf]);
    }
#pragma unroll
    for (int mi = 0; mi < 2; mi++) {
        if (diag) mask_half(s1[mi], 4, colbase, t0 + mi * 16, cp0);
        conv_half(s1[mi], af[mi], 2);
    }
#pragma unroll
    for (int ks = 2; ks < 4; ks++) {
        uint32_t bf[8][2];
        load_b_t1(s2b, ks * 16, lane, bf);
#pragma unroll
        for (int mi = 0; mi < 2; mi++)
#pragma unroll
            for (int nf = 0; nf < 8; nf++) mma16816(acc[mi][nf], af[mi][ks], bf[nf]);
    }
}

// ---------------------------------------------------------------------------
// cp.async (128 threads)
// ---------------------------------------------------------------------------
__device__ __forceinline__ void cpa16(uint32_t smaddr, const void* gaddr) {
    asm volatile("cp.async.cg.shared.global [%0], [%1], 16;" :: "r"(smaddr), "l"(gaddr));
}
__device__ __forceinline__ void issue_panel1(const uint32_t* g, uint32_t sm, int tid) {
    for (int i = tid; i < 512; i += 128) {
        int r = i >> 3, c = i & 7;
        uint32_t off = sw128((uint32_t)(r * 128 + c * 16));
        cpa16(sm + off, g + r * 32 + c * 4);
    }
}
#define CP_COMMIT() asm volatile("cp.async.commit_group;" ::: "memory")
#define CP_WAIT1()  asm volatile("cp.async.wait_group 1;" ::: "memory")
#define CP_WAIT0()  asm volatile("cp.async.wait_group 0;" ::: "memory")

// ===========================================================================
// Preprocess: k/v only -> fp16, head-major rows of 64 (q handled in fused)
// ===========================================================================
__global__ __launch_bounds__(256) void prep(const float* __restrict__ qkv) {
    int idx = blockIdx.x * 256 + threadIdx.x;
    int c2 = idx & 31;
    int h  = (idx >> 5) & 15;
    int w  = (idx >> 9) % 3;
    if (w == 0) return;
    int sb = idx / 1536;
    int s  = sb & (S_ - 1);
    int b  = sb >> 11;
    float2 v = *reinterpret_cast<const float2*>(qkv + (size_t)idx * 2);
    size_t dst = ((size_t)(b * 16 + h) * S_ + s) * 32 + c2;
    uint32_t p = pack_f16(v.x, v.y);
    if (w == 1) g_k[dst] = p;
    else        g_v[dst] = p;
}

// smem: V ring 6 x 8K = [0,48K) (q staging [0,16K) aliases V0/V1)
//       K ring 6 x 8K = [48K,96K)
#define SMV(st) ((st) * 8192)
#define SMK(st) (49152 + (st) * 8192)
#define SMEM_BYTES 98304

// ===========================================================================
// Fused, 128 threads / 4 warps, m32 tiles, 2-chunk super-iterations.
// phase 1: o2 = tril(q kT) k, u = (2q-o2)/16 in REGISTERS (aF union)
// phase 2: out = tril(u kT) v * 16
// ===========================================================================
__global__ __launch_bounds__(128, 2) void fused(const float* __restrict__ qkv,
                                                float* __restrict__ out) {
    int bh = blockIdx.y, tt = 15 - (int)blockIdx.x;
    extern __shared__ __align__(1024) char smem[];
    uint32_t sb = smem_u32(smem);
    int tid = threadIdx.x, lane = tid & 31, wid = tid >> 5;
    int warp_m = wid * 32;
    int b = bh >> 4, h = bh & 15;
    int nch = 2 * tt + 2;
    int nit = nch >> 1;               // nch always even

    const uint32_t* k0 = g_k + (size_t)bh * S_ * 32;
    const uint32_t* v0 = g_v + (size_t)bh * S_ * 32;

    // prologue: stage q straight from fp32 qkv (w=0 plane), convert to fp16
    {
        const float* qsrc = qkv + ((size_t)(b * S_ + tt * 128) * 3) * (H_ * D_) + h * D_;
        for (int idx = tid; idx < 128 * 32; idx += 128) {
            int r = idx >> 5, c2 = idx & 31;
            float2 v = *reinterpret_cast<const float2*>(qsrc + (size_t)r * 3072 + c2 * 2);
            uint32_t off = sw128((uint32_t)(r * 128 + c2 * 4));
            *reinterpret_cast<uint32_t*>(smem + off) = pack_f16(v.x, v.y);
        }
    }
    // prefetch k iterations 0 (chunks 0,1) and 1 (chunks 2,3)
    issue_panel1(k0, sb + SMK(0), tid);
    issue_panel1(k0 + 2048, sb + SMK(1), tid);
    CP_COMMIT();
    if (nit > 1) {
        issue_panel1(k0 + 2 * 2048, sb + SMK(2), tid);
        issue_panel1(k0 + 3 * 2048, sb + SMK(3), tid);
        CP_COMMIT();
    }
    __syncthreads();

    // aF holds q-frags now, u-frags after the seam (register union)
    uint32_t aF[2][4][4];
#pragma unroll
    for (int mi = 0; mi < 2; mi++)
#pragma unroll
        for (int kf = 0; kf < 4; kf++)
            ldsm_x4(sb, warp_m + mi * 16, kf * 16, lane, aF[mi][kf]);

    int t0 = tt * 128 + warp_m + (lane >> 2);
    int cp0 = (lane & 3) * 2;
    int row_hi = tt * 128 + warp_m + 31;

    // ---------------- phase 1: o2 ----------------
    float o2acc[2][8][4] = {};
    for (int it = 0; it < nit; it++) {
        if (it + 1 < nit) CP_WAIT1(); else CP_WAIT0();
        __syncthreads();
        if (it + 2 < nit) {
            int c = 2 * it + 4;
            issue_panel1(k0 + (size_t)c * 2048,       sb + SMK(c % 6), tid);
            issue_panel1(k0 + (size_t)(c + 1) * 2048, sb + SMK((c + 1) % 6), tid);
            CP_COMMIT();
        }
#pragma unroll
        for (int sub = 0; sub < 2; sub++) {
            int ch = 2 * it + sub;
            if (ch * 64 <= row_hi) {
                uint32_t kb = sb + SMK(ch % 6);
                chunk_gemm(kb, kb, aF, o2acc, lane, t0, cp0, ch * 64, ch >= 2 * tt);
            }
        }
    }

    // phase-2 prefetch (before u-conversion). k slots offset by koff so prologue
    // writes never touch slots straggler warps may still read ((nch-2..nch-1)%6).
    int koff = nch % 6;
    issue_panel1(k0, sb + SMK(koff), tid);
    issue_panel1(k0 + 2048, sb + SMK((koff + 1) % 6), tid);
    issue_panel1(v0, sb + SMV(0), tid);
    issue_panel1(v0 + 2048, sb + SMV(1), tid);
    CP_COMMIT();
    if (nit > 1) {
        issue_panel1(k0 + 2 * 2048, sb + SMK((koff + 2) % 6), tid);
        issue_panel1(k0 + 3 * 2048, sb + SMK((koff + 3) % 6), tid);
        issue_panel1(v0 + 2 * 2048, sb + SMV(2), tid);
        issue_panel1(v0 + 3 * 2048, sb + SMV(3), tid);
        CP_COMMIT();
    }

    // seam: u = (2q - o2) * U_SCALE, overwriting aF (acc layout == A-frag layout)
#pragma unroll
    for (int mi = 0; mi < 2; mi++) {
        float uacc[8][4];
#pragma unroll
        for (int nf = 0; nf < 8; nf++)
#pragma unroll
            for (int half = 0; half < 2; half++) {
                int reg = ((nf & 1) << 1) | half;
                uint32_t qb = aF[mi][nf >> 1][reg];
                float q0 = __half2float(__ushort_as_half((unsigned short)(qb & 0xFFFF)));
                float q1 = __half2float(__ushort_as_half((unsigned short)(qb >> 16)));
                uacc[nf][half * 2 + 0] = (2.0f * q0 - o2acc[mi][nf][half * 2 + 0]) * U_SCALE;
                uacc[nf][half * 2 + 1] = (2.0f * q1 - o2acc[mi][nf][half * 2 + 1]) * U_SCALE;
            }
#pragma unroll
        for (int kf = 0; kf < 4; kf++) {
            aF[mi][kf][0] = pack_f16(uacc[2*kf  ][0], uacc[2*kf  ][1]);
            aF[mi][kf][1] = pack_f16(uacc[2*kf  ][2], uacc[2*kf  ][3]);
            aF[mi][kf][2] = pack_f16(uacc[2*kf+1][0], uacc[2*kf+1][1]);
            aF[mi][kf][3] = pack_f16(uacc[2*kf+1][2], uacc[2*kf+1][3]);
        }
    }

    // ---------------- phase 2: out ----------------
    float outacc[2][8][4] = {};
    for (int it = 0; it < nit; it++) {
        if (it + 1 < nit) CP_WAIT1(); else CP_WAIT0();
        __syncthreads();
        if (it + 2 < nit) {
            int c = 2 * it + 4;
            issue_panel1(k0 + (size_t)c * 2048,       sb + SMK((koff + c) % 6), tid);
            issue_panel1(k0 + (size_t)(c + 1) * 2048, sb + SMK((koff + c + 1) % 6), tid);
            issue_panel1(v0 + (size_t)c * 2048,       sb + SMV(c % 6), tid);
            issue_panel1(v0 + (size_t)(c + 1) * 2048, sb + SMV((c + 1) % 6), tid);
            CP_COMMIT();
        }
#pragma unroll
        for (int sub = 0; sub < 2; sub++) {
            int ch = 2 * it + sub;
            if (ch * 64 <= row_hi) {
                uint32_t kb = sb + SMK((koff + ch) % 6);
                uint32_t vb = sb + SMV(ch % 6);
                chunk_gemm(kb, vb, aF, outacc, lane, t0, cp0, ch * 64, ch >= 2 * tt);
            }
        }
    }

    // out (B,S,H,D) fp32, undo U_SCALE
#pragma unroll
    for (int mi = 0; mi < 2; mi++)
#pragma unroll
        for (int half = 0; half < 2; half++) {
            int t = t0 + mi * 16 + half * 8;
            float* op = out + (((size_t)(b * S_ + t)) * 16 + h) * 64;
#pragma unroll
            for (int nf = 0; nf < 8; nf++) {
                float2 v = make_float2(outacc[mi][nf][half * 2 + 0] * U_UNSCALE,
                                       outacc[mi][nf][half * 2 + 1] * U_UNSCALE);
                *reinterpret_cast<float2*>(op + nf * 8 + cp0) = v;
            }
        }
}

// ===========================================================================
extern "C" void kernel_launch(void* const* d_in, const int* in_sizes, int n_in,
                              void* d_out, int out_size) {
    const float* qkv = (const float*)d_in[0];
    float* out = (float*)d_out;

    static bool attr_done = false;
    if (!attr_done) {
        cudaFuncSetAttribute(fused, cudaFuncAttributeMaxDynamicSharedMemorySize, SMEM_BYTES);
        attr_done = true;
    }

    prep<<<B_ * S_ * 3 * H_ * 32 / 256, 256>>>(qkv);
    dim3 grid(16, BH_);
    fused<<<grid, 128, SMEM_BYTES>>>(qkv, out);
}

// round 16
// speedup vs baseline: 1.6493x; 1.5270x over previous
#include <cuda_runtime.h>
#include <cuda_fp16.h>
#include <cstdint>

// Problem constants: qkv (B,S,3,H,D) fp32
#define B_   2
#define S_   2048
#define H_   16
#define D_   64
#define BH_  32

#define U_SCALE   0.0625f
#define U_UNSCALE 16.0f

__device__ uint32_t g_k[(size_t)BH_ * S_ * 32];
__device__ uint32_t g_v[(size_t)BH_ * S_ * 32];

__device__ __forceinline__ uint32_t smem_u32(const void* p) {
    uint32_t a;
    asm("{ .reg .u64 t; cvta.to.shared.u64 t, %1; cvt.u32.u64 %0, t; }" : "=r"(a) : "l"(p));
    return a;
}
__device__ __forceinline__ uint32_t sw128(uint32_t off) { return off ^ ((off >> 3) & 0x70); }

__device__ __forceinline__ uint32_t pack_f16(float x0, float x1) {
    uint32_t r;
    asm("cvt.rn.f16x2.f32 %0, %1, %2;" : "=r"(r) : "f"(x1), "f"(x0));
    return r;
}

// ---------------------------------------------------------------------------
// ldmatrix / mma (fragment mappings validated rounds 3-15)
// ---------------------------------------------------------------------------
__device__ __forceinline__ void ldsm_x4(uint32_t base, int r_base, int c_base, int lane, uint32_t r[4]) {
    uint32_t off = (uint32_t)((r_base + (lane & 15)) * 128 + (c_base + ((lane >> 4) << 3)) * 2);
    uint32_t addr = base + sw128(off);
    asm volatile("ldmatrix.sync.aligned.m8n8.x4.shared.b16 {%0,%1,%2,%3}, [%4];"
                 : "=r"(r[0]), "=r"(r[1]), "=r"(r[2]), "=r"(r[3]) : "r"(addr));
}
__device__ __forceinline__ void ldsm_x4_t(uint32_t base, int r_base, int c_base, int lane, uint32_t r[4]) {
    uint32_t off = (uint32_t)((r_base + (lane & 15)) * 128 + (c_base + ((lane >> 4) << 3)) * 2);
    uint32_t addr = base + sw128(off);
    asm volatile("ldmatrix.sync.aligned.m8n8.x4.trans.shared.b16 {%0,%1,%2,%3}, [%4];"
                 : "=r"(r[0]), "=r"(r[1]), "=r"(r[2]), "=r"(r[3]) : "r"(addr));
}
__device__ __forceinline__ void mma16816(float c[4], const uint32_t a[4], const uint32_t b[2]) {
    asm volatile("mma.sync.aligned.m16n8k16.row.col.f32.f16.f16.f32 "
                 "{%0,%1,%2,%3}, {%4,%5,%6,%7}, {%8,%9}, {%0,%1,%2,%3};"
                 : "+f"(c[0]), "+f"(c[1]), "+f"(c[2]), "+f"(c[3])
                 : "r"(a[0]), "r"(a[1]), "r"(a[2]), "r"(a[3]), "r"(b[0]), "r"(b[1]));
}

// B-frags, trans ([k][n]), n=64 (stage 2)
__device__ __forceinline__ void load_b_t1(uint32_t base, int kk, int lane, uint32_t bf[8][2]) {
#pragma unroll
    for (int nq = 0; nq < 4; nq++) {
        uint32_t r[4];
        ldsm_x4_t(base, kk, nq * 16, lane, r);
        bf[2*nq][0] = r[0]; bf[2*nq][1] = r[1]; bf[2*nq+1][0] = r[2]; bf[2*nq+1][1] = r[3];
    }
}

// mask a half (4 nf frags starting at nfbase) of one m16 subtile
__device__ __forceinline__ void mask_half(float (&s1)[8][4], int nfbase, int colbase,
                                          int t0mi, int cp0) {
#pragma unroll
    for (int nf = 0; nf < 4; nf++)
#pragma unroll
        for (int e = 0; e < 4; e++) {
            int srow = t0mi + ((e >> 1) << 3);
            int scol = colbase + (nfbase + nf) * 8 + cp0 + (e & 1);
            if (scol > srow) s1[nfbase + nf][e] = 0.0f;
        }
}
// conv a half: s1[2kf],s1[2kf+1] -> af[kf], for kf in {kfbase, kfbase+1}
__device__ __forceinline__ void conv_half(const float (&s1)[8][4], uint32_t (&af)[4][4], int kfbase) {
#pragma unroll
    for (int kf = kfbase; kf < kfbase + 2; kf++) {
        af[kf][0] = pack_f16(s1[2*kf  ][0], s1[2*kf  ][1]);
        af[kf][1] = pack_f16(s1[2*kf  ][2], s1[2*kf  ][3]);
        af[kf][2] = pack_f16(s1[2*kf+1][0], s1[2*kf+1][1]);
        af[kf][3] = pack_f16(s1[2*kf+1][2], s1[2*kf+1][3]);
    }
}

// ---------------------------------------------------------------------------
// One 64-col chunk for an m32 warp tile (R12-proven body)
// ---------------------------------------------------------------------------
__device__ __forceinline__ void chunk_gemm(uint32_t kb, uint32_t s2b,
                                           const uint32_t (&aF)[2][4][4], float (&acc)[2][8][4],
                                           int lane, int t0, int cp0, int colbase, bool diag) {
    float s1[2][8][4] = {};
#pragma unroll
    for (int kd = 0; kd < 4; kd++) {
        uint32_t r0[4], r1[4];
        ldsm_x4(kb, 0,  kd * 16, lane, r0);
        ldsm_x4(kb, 16, kd * 16, lane, r1);
        uint32_t bf[4][2];
        bf[0][0] = r0[0]; bf[0][1] = r0[2]; bf[1][0] = r0[1]; bf[1][1] = r0[3];
        bf[2][0] = r1[0]; bf[2][1] = r1[2]; bf[3][0] = r1[1]; bf[3][1] = r1[3];
#pragma unroll
        for (int mi = 0; mi < 2; mi++)
#pragma unroll
            for (int nf = 0; nf < 4; nf++) mma16816(s1[mi][nf], aF[mi][kd], bf[nf]);
    }
#pragma unroll
    for (int kd = 0; kd < 4; kd++) {
        uint32_t r0[4], r1[4];
        ldsm_x4(kb, 32, kd * 16, lane, r0);
        ldsm_x4(kb, 48, kd * 16, lane, r1);
        uint32_t bf[4][2];
        bf[0][0] = r0[0]; bf[0][1] = r0[2]; bf[1][0] = r0[1]; bf[1][1] = r0[3];
        bf[2][0] = r1[0]; bf[2][1] = r1[2]; bf[3][0] = r1[1]; bf[3][1] = r1[3];
#pragma unroll
        for (int mi = 0; mi < 2; mi++)
#pragma unroll
            for (int nf = 0; nf < 4; nf++) mma16816(s1[mi][4 + nf], aF[mi][kd], bf[nf]);
    }
    uint32_t af[2][4][4];
#pragma unroll
    for (int mi = 0; mi < 2; mi++) {
        if (diag) mask_half(s1[mi], 0, colbase, t0 + mi * 16, cp0);
        conv_half(s1[mi], af[mi], 0);
    }
#pragma unroll
    for (int ks = 0; ks < 2; ks++) {
        uint32_t bf[8][2];
        load_b_t1(s2b, ks * 16, lane, bf);
#pragma unroll
        for (int mi = 0; mi < 2; mi++)
#pragma unroll
            for (int nf = 0; nf < 8; nf++) mma16816(acc[mi][nf], af[mi][ks], bf[nf]);
    }
#pragma unroll
    for (int mi = 0; mi < 2; mi++) {
        if (diag) mask_half(s1[mi], 4, colbase, t0 + mi * 16, cp0);
        conv_half(s1[mi], af[mi], 2);
    }
#pragma unroll
    for (int ks = 2; ks < 4; ks++) {
        uint32_t bf[8][2];
        load_b_t1(s2b, ks * 16, lane, bf);
#pragma unroll
        for (int mi = 0; mi < 2; mi++)
#pragma unroll
            for (int nf = 0; nf < 8; nf++) mma16816(acc[mi][nf], af[mi][ks], bf[nf]);
    }
}

// ---------------------------------------------------------------------------
// cp.async: single 64-row x 128B panel, SW128 swizzled (128 threads)
// ---------------------------------------------------------------------------
__device__ __forceinline__ void cpa16(uint32_t smaddr, const void* gaddr) {
    asm volatile("cp.async.cg.shared.global [%0], [%1], 16;" :: "r"(smaddr), "l"(gaddr));
}
__device__ __forceinline__ void issue_panel1(const uint32_t* g, uint32_t sm, int tid) {
    for (int i = tid; i < 512; i += 128) {
        int r = i >> 3, c = i & 7;
        uint32_t off = sw128((uint32_t)(r * 128 + c * 16));
        cpa16(sm + off, g + r * 32 + c * 4);
    }
}
#define CP_COMMIT() asm volatile("cp.async.commit_group;" ::: "memory")
#define CP_WAIT1()  asm volatile("cp.async.wait_group 1;" ::: "memory")
#define CP_WAIT0()  asm volatile("cp.async.wait_group 0;" ::: "memory")

// ===========================================================================
// Preprocess: k/v only -> fp16, head-major rows of 64. float4-vectorized.
// One thread per 4 floats of the k/v planes.
// ===========================================================================
__global__ __launch_bounds__(256) void prep(const float* __restrict__ qkv) {
    int idx = blockIdx.x * 256 + threadIdx.x;       // B*S*2*H*16 threads
    int c4 = idx & 15;                              // 16 float4 per 64-float row
    int h  = (idx >> 4) & 15;
    int w2 = (idx >> 8) & 1;                        // 0 = k, 1 = v
    int sb = idx >> 9;
    int s  = sb & (S_ - 1);
    int b  = sb >> 11;
    const float* src = qkv + ((size_t)(b * S_ + s) * 3 + (w2 + 1)) * (H_ * D_) + h * D_ + c4 * 4;
    float4 v = *reinterpret_cast<const float4*>(src);
    uint32_t p0 = pack_f16(v.x, v.y);
    uint32_t p1 = pack_f16(v.z, v.w);
    size_t dst = ((size_t)(b * 16 + h) * S_ + s) * 32 + c4 * 2;
    uint32_t* g = w2 ? g_v : g_k;
    g[dst] = p0; g[dst + 1] = p1;
}

// smem: V ring [0,24K) (q staging [0,16K) aliases V0/V1, dead before phase 2)
//       K ring [24K,48K)
#define SMQ 0
#define SMV(st) ((st) * 8192)
#define SMK(st) (24576 + (st) * 8192)
#define SMEM_BYTES 49152

// ===========================================================================
// Fused, 128 threads / 4 warps, m32 warp tiles (R12 structure).
// phase 1: o2 = tril(q kT) k, u = (2q-o2)/16 in REGISTERS
// phase 2: out = tril(u kT) v * 16
// ===========================================================================
__global__ __launch_bounds__(128, 2) void fused(const float* __restrict__ qkv,
                                                float* __restrict__ out) {
    int bh = blockIdx.y, tt = 15 - (int)blockIdx.x;
    extern __shared__ __align__(1024) char smem[];
    uint32_t sb = smem_u32(smem);
    int tid = threadIdx.x, lane = tid & 31, wid = tid >> 5;
    int warp_m = wid * 32;
    int b = bh >> 4, h = bh & 15;
    int nch = 2 * tt + 2;

    const uint32_t* k0 = g_k + (size_t)bh * S_ * 32;
    const uint32_t* v0 = g_v + (size_t)bh * S_ * 32;

    // prologue: stage q straight from fp32 qkv (w=0 plane), fp16-convert into smem
    {
        const float* qsrc = qkv + ((size_t)(b * S_ + tt * 128) * 3) * (H_ * D_) + h * D_;
        for (int idx = tid; idx < 128 * 16; idx += 128) {
            int r = idx >> 4, c4 = idx & 15;
            float4 v = *reinterpret_cast<const float4*>(qsrc + (size_t)r * 3072 + c4 * 4);
            uint32_t off0 = sw128((uint32_t)(r * 128 + c4 * 8));
            uint32_t off1 = sw128((uint32_t)(r * 128 + c4 * 8 + 4));
            *reinterpret_cast<uint32_t*>(smem + off0) = pack_f16(v.x, v.y);
            *reinterpret_cast<uint32_t*>(smem + off1) = pack_f16(v.z, v.w);
        }
    }
    issue_panel1(k0, sb + SMK(0), tid);
    CP_COMMIT();
    issue_panel1(k0 + 2048, sb + SMK(1), tid);
    CP_COMMIT();
    __syncthreads();

    uint32_t qf[2][4][4];
#pragma unroll
    for (int mi = 0; mi < 2; mi++)
#pragma unroll
        for (int kf = 0; kf < 4; kf++)
            ldsm_x4(sb + SMQ, warp_m + mi * 16, kf * 16, lane, qf[mi][kf]);

    int t0 = tt * 128 + warp_m + (lane >> 2);
    int cp0 = (lane & 3) * 2;
    int row_hi = tt * 128 + warp_m + 31;

    // ---------------- phase 1: o2 ----------------
    float o2acc[2][8][4] = {};
    for (int ch = 0; ch < nch; ch++) {
        if (ch + 1 < nch) CP_WAIT1(); else CP_WAIT0();
        __syncthreads();
        if (ch + 2 < nch) {
            issue_panel1(k0 + (size_t)(ch + 2) * 2048, sb + SMK((ch + 2) % 3), tid);
            CP_COMMIT();
        }
        if (ch * 64 <= row_hi) {
            uint32_t kb = sb + SMK(ch % 3);
            chunk_gemm(kb, kb, qf, o2acc, lane, t0, cp0, ch * 64, ch >= 2 * tt);
        }
    }

    // phase-2 prefetch before u-conversion (overlap DMA with math).
    int kb0 = nch % 3;
    issue_panel1(k0, sb + SMK(kb0), tid);
    issue_panel1(v0, sb + SMV(0), tid);
    CP_COMMIT();
    issue_panel1(k0 + 2048, sb + SMK((kb0 + 1) % 3), tid);
    issue_panel1(v0 + 2048, sb + SMV(1), tid);
    CP_COMMIT();

    // u = (2q - o2) * U_SCALE directly into A-frags (acc layout == A-frag layout)
    uint32_t uf[2][4][4];
#pragma unroll
    for (int mi = 0; mi < 2; mi++) {
        float uacc[8][4];
#pragma unroll
        for (int nf = 0; nf < 8; nf++)
#pragma unroll
            for (int half = 0; half < 2; half++) {
                int reg = ((nf & 1) << 1) | half;
                uint32_t qb = qf[mi][nf >> 1][reg];
                float q0 = __half2float(__ushort_as_half((unsigned short)(qb & 0xFFFF)));
                float q1 = __half2float(__ushort_as_half((unsigned short)(qb >> 16)));
                uacc[nf][half * 2 + 0] = (2.0f * q0 - o2acc[mi][nf][half * 2 + 0]) * U_SCALE;
                uacc[nf][half * 2 + 1] = (2.0f * q1 - o2acc[mi][nf][half * 2 + 1]) * U_SCALE;
            }
#pragma unroll
        for (int kf = 0; kf < 4; kf++) {
            uf[mi][kf][0] = pack_f16(uacc[2*kf  ][0], uacc[2*kf  ][1]);
            uf[mi][kf][1] = pack_f16(uacc[2*kf  ][2], uacc[2*kf  ][3]);
            uf[mi][kf][2] = pack_f16(uacc[2*kf+1][0], uacc[2*kf+1][1]);
            uf[mi][kf][3] = pack_f16(uacc[2*kf+1][2], uacc[2*kf+1][3]);
        }
    }

    // ---------------- phase 2: out ----------------
    float outacc[2][8][4] = {};
    for (int ch = 0; ch < nch; ch++) {
        if (ch + 1 < nch) CP_WAIT1(); else CP_WAIT0();
        __syncthreads();
        if (ch + 2 < nch) {
            issue_panel1(k0 + (size_t)(ch + 2) * 2048, sb + SMK((kb0 + ch + 2) % 3), tid);
            issue_panel1(v0 + (size_t)(ch + 2) * 2048, sb + SMV((ch + 2) % 3), tid);
            CP_COMMIT();
        }
        if (ch * 64 <= row_hi) {
            uint32_t kb = sb + SMK((kb0 + ch) % 3);
            uint32_t vb = sb + SMV(ch % 3);
            chunk_gemm(kb, vb, uf, outacc, lane, t0, cp0, ch * 64, ch >= 2 * tt);
        }
    }

    // out (B,S,H,D) fp32, undo U_SCALE
#pragma unroll
    for (int mi = 0; mi < 2; mi++)
#pragma unroll
        for (int half = 0; half < 2; half++) {
            int t = t0 + mi * 16 + half * 8;
            float* op = out + (((size_t)(b * S_ + t)) * 16 + h) * 64;
#pragma unroll
            for (int nf = 0; nf < 8; nf++) {
                float2 v = make_float2(outacc[mi][nf][half * 2 + 0] * U_UNSCALE,
                                       outacc[mi][nf][half * 2 + 1] * U_UNSCALE);
                *reinterpret_cast<float2*>(op + nf * 8 + cp0) = v;
            }
        }
}

// ===========================================================================
extern "C" void kernel_launch(void* const* d_in, const int* in_sizes, int n_in,
                              void* d_out, int out_size) {
    const float* qkv = (const float*)d_in[0];
    float* out = (float*)d_out;

    static bool attr_done = false;
    if (!attr_done) {
        cudaFuncSetAttribute(fused, cudaFuncAttributeMaxDynamicSharedMemorySize, SMEM_BYTES);
        attr_done = true;
    }

    // k/v planes only: B*S*2*H*16 threads, float4 per thread
    prep<<<B_ * S_ * 2 * H_ * 16 / 256, 256>>>(qkv);
    dim3 grid(16, BH_);
    fused<<<grid, 128, SMEM_BYTES>>>(qkv, out);
}